// round 15
// baseline (speedup 1.0000x reference)
#include <cuda_runtime.h>
#include <cstdint>

#define NSESS    4096
#define NTRIALS  2048
#define NWORDS   (NTRIALS / 32)        // 64 packed words per session

// filter chunking (R13-proven)
#define FCHUNK   32                    // output trials per warp (1 packed word)
#define FNCHUNK  (NTRIALS / FCHUNK)    // 64 chunks
#define FWARM    16                    // warmup trials (validated: rel_err ~6e-5)

// 2-way session pipeline
#define HALF     (NSESS / 2)           // 2048 sessions per half

// packed bits: bit i of packed[w*NSESS+s] = (chose_left==outcome) at trial w*32+i
__device__ uint32_t g_packed[NWORDS * NSESS];

__device__ __forceinline__ float frcp_fast(float x) {
    float y;
    asm("rcp.approx.f32 %0, %1;" : "=f"(y) : "f"(x));
    return y;
}

__device__ __forceinline__ void cp_async16(uint32_t dst, const void* src) {
    asm volatile("cp.async.cg.shared.global [%0], [%1], 16;\n" :: "r"(dst), "l"(src));
}
__device__ __forceinline__ void cp_commit() {
    asm volatile("cp.async.commit_group;\n" ::: "memory");
}
template <int N>
__device__ __forceinline__ void cp_wait() {
    asm volatile("cp.async.wait_group %0;\n" :: "n"(N) : "memory");
}

// ---------------------------------------------------------------------------
// Kernel 1: pack (R14 4-deep prefetch, proven). One warp per QUARTER-session;
// parameterized by session base for the pipeline split.
// ---------------------------------------------------------------------------
#define PTILE 1536

__global__ void __launch_bounds__(128)
pack_kernel(const float* __restrict__ in, uint32_t* __restrict__ packed,
            int sess_base) {
    __shared__ __align__(16) char buf[4][4][PTILE];   // 24576 B

    const int lane  = threadIdx.x & 31;
    const int wid   = threadIdx.x >> 5;
    const int gwarp = blockIdx.x * 4 + wid;
    const int s     = sess_base + (gwarp >> 2);
    const int quart = gwarp & 3;

    const char* src = (const char*)in + (long)s * (NTRIALS * 12) + quart * (512 * 12);
    const uint32_t sbase = (uint32_t)__cvta_generic_to_shared(&buf[wid][0][0]);

#pragma unroll
    for (int t = 0; t < 4; t++) {
#pragma unroll
        for (int r = 0; r < 3; r++)
            cp_async16(sbase + t * PTILE + r * 512 + lane * 16,
                       src + t * PTILE + r * 512 + lane * 16);
        cp_commit();
    }

#pragma unroll
    for (int t = 0; t < 4; t++) {
        switch (t) {
            case 0: cp_wait<3>(); break;
            case 1: cp_wait<2>(); break;
            case 2: cp_wait<1>(); break;
            default: cp_wait<0>(); break;
        }
        __syncwarp();

        const float4* rp = (const float4*)(&buf[wid][t][0] + 48 * lane);
        float4 x0 = rp[0];   // cl0 cr0 o0  cl1
        float4 x1 = rp[1];   // cr1 o1  cl2 cr2
        float4 x2 = rp[2];   // o2  cl3 cr3 o3

        int b0 = (x0.x == x0.z);
        int b1 = (x0.w == x1.y);
        int b2 = (x1.z == x2.x);
        int b3 = (x2.y == x2.w);
        uint32_t nib = (uint32_t)(b0 | (b1 << 1) | (b2 << 2) | (b3 << 3));
        uint32_t v = nib << ((lane & 7) * 4);
        v |= __shfl_xor_sync(0xFFFFFFFFu, v, 1);
        v |= __shfl_xor_sync(0xFFFFFFFFu, v, 2);
        v |= __shfl_xor_sync(0xFFFFFFFFu, v, 4);
        if ((lane & 7) == 0) {
            int w = quart * 16 + t * 4 + (lane >> 3);
            packed[w * NSESS + s] = v;
        }
    }
}

// ---------------------------------------------------------------------------
// Kernel 2: filter (R13-proven: FCHUNK=32, ALU-coefficient form, no klut LDS).
// Parameterized by session base.
// ---------------------------------------------------------------------------
#define ROW_F4 9
#define WARP_F4 (32 * ROW_F4)

__global__ void __launch_bounds__(128, 10)
filter_kernel(const uint32_t* __restrict__ packed,
              const float* __restrict__ p_stay_raw,
              const float* __restrict__ c_raw,
              float* __restrict__ out,
              int sess_base) {
    __shared__ float4 stage4[4 * WARP_F4];   // 18432 B

    const int lane  = threadIdx.x & 31;
    const int wid   = threadIdx.x >> 5;
    const int gwarp = blockIdx.x * 4 + wid;
    const int chunk = gwarp & (FNCHUNK - 1);
    const int sess0 = sess_base + (gwarp >> 6) * 32;   // FNCHUNK == 64

    const uint32_t wcur = packed[chunk * NSESS + sess0 + lane];
    const uint32_t wprev = (chunk > 0)
        ? packed[(chunk - 1) * NSESS + sess0 + lane] : 0u;

    const float pv = 1.0f / (1.0f + __expf(-p_stay_raw[0]));
    const float cv = 1.0f / (1.0f + __expf(-c_raw[0]));
    const float A  = 0.5f * (1.0f + cv);
    const float B  = 0.5f * (1.0f - cv);
    const float q  = 0.5f * (1.0f + pv);
    const float qm = 0.5f * (1.0f - pv);

    float4* ws4 = stage4 + wid * WARP_F4;
    float4* ob4 = ws4 + lane * ROW_F4;

    float v0 = 0.5f, v1 = 0.5f;

    if (chunk > 0) {
#pragma unroll
        for (int i = 0; i < FWARM; i++) {
            float e0 = ((wprev >> (16 + i)) & 1u) ? A : B;
            float u0 = e0 * v0;
            float u1 = fmaf(-e0, v1, v1);
            float s  = u0 + u1;
            float a  = fmaf(q, u0, qm * u1);
            v0 = a;
            v1 = s - a;
        }
        float r = frcp_fast(v0 + v1);
        v0 *= r; v1 *= r;
    }

#pragma unroll
    for (int h = 0; h < 2; h++) {
        float r_mid = 1.0f;
        float px = 0.0f;
#pragma unroll
        for (int i = 0; i < 16; i++) {
            float e0 = ((wcur >> (h * 16 + i)) & 1u) ? A : B;
            float u0 = e0 * v0;
            float u1 = fmaf(-e0, v1, v1);
            float s  = u0 + u1;
            float a  = fmaf(q, u0, qm * u1);
            float r  = frcp_fast(s);       // off-chain: outputs only
            float x  = a * r;
            if (i & 1) {
                ob4[i >> 1] = make_float4(px, 1.0f - px, x, 1.0f - x);
            } else {
                px = x;
            }
            if (i == 7) r_mid = r;
            v0 = a;
            v1 = s - a;
        }
        v0 *= r_mid; v1 *= r_mid;

        __syncwarp();
        const int T = chunk * 32 + h * 16;
        float4* og4 = (float4*)out + (long)sess0 * (NTRIALS / 2) + (T >> 1);
#pragma unroll
        for (int j = 0; j < 8; j++) {
            int idx = j * 32 + lane;
            int row = idx >> 3;
            int col = idx & 7;
            og4[(long)row * (NTRIALS / 2) + col] = ws4[row * ROW_F4 + col];
        }
        __syncwarp();
    }
}

// ---------------------------------------------------------------------------
// Launch: 2-way session pipeline.
//   main: P_A ─ eA ─► F_A ─(wait eB)─► F_B
//   s2:   (wait eA) P_B ─ eB
// Host-side stream/event objects only; serial fallback if creation fails.
// ---------------------------------------------------------------------------
extern "C" void kernel_launch(void* const* d_in, const int* in_sizes, int n_in,
                              void* d_out, int out_size) {
    const float* in   = (const float*)d_in[0];
    const float* praw = (const float*)d_in[1];
    const float* craw = (const float*)d_in[2];
    float* out = (float*)d_out;

    uint32_t* packed = nullptr;
    cudaGetSymbolAddress((void**)&packed, g_packed);

    const int PACK_BLKS = HALF;                        // 2048 blocks per half
    const int FILT_BLKS = (HALF / 32) * FNCHUNK / 4;   // 1024 blocks per half

    cudaStream_t s2 = nullptr;
    if (cudaStreamCreateWithFlags(&s2, cudaStreamNonBlocking) != cudaSuccess) {
        // serial fallback (== R13 behavior)
        pack_kernel<<<PACK_BLKS, 128>>>(in, packed, 0);
        pack_kernel<<<PACK_BLKS, 128>>>(in, packed, HALF);
        filter_kernel<<<FILT_BLKS, 128>>>(packed, praw, craw, out, 0);
        filter_kernel<<<FILT_BLKS, 128>>>(packed, praw, craw, out, HALF);
        return;
    }

    cudaEvent_t eA, eB;
    cudaEventCreateWithFlags(&eA, cudaEventDisableTiming);
    cudaEventCreateWithFlags(&eB, cudaEventDisableTiming);

    // P_A on main
    pack_kernel<<<PACK_BLKS, 128>>>(in, packed, 0);
    cudaEventRecord(eA, 0);

    // P_B on s2, after P_A (keeps full read BW for each pack phase)
    cudaStreamWaitEvent(s2, eA, 0);
    pack_kernel<<<PACK_BLKS, 128, 0, s2>>>(in, packed, HALF);
    cudaEventRecord(eB, s2);

    // F_A on main overlaps P_B; F_B after P_B
    filter_kernel<<<FILT_BLKS, 128>>>(packed, praw, craw, out, 0);
    cudaStreamWaitEvent(0, eB, 0);
    filter_kernel<<<FILT_BLKS, 128>>>(packed, praw, craw, out, HALF);
}

// round 16
// speedup vs baseline: 1.3482x; 1.3482x over previous
#include <cuda_runtime.h>
#include <cstdint>

#define NSESS   4096
#define NTRIALS 2048
#define HALFT   1024            // trials per warp (half session)
#define FWARM   16              // warmup trials (validated: rel_err ~6e-5)

__device__ __forceinline__ float frcp_fast(float x) {
    float y;
    asm("rcp.approx.f32 %0, %1;" : "=f"(y) : "f"(x));
    return y;
}

__device__ __forceinline__ void cp_async16(uint32_t dst, const void* src) {
    asm volatile("cp.async.cg.shared.global [%0], [%1], 16;\n" :: "r"(dst), "l"(src));
}
__device__ __forceinline__ void cp_commit() {
    asm volatile("cp.async.commit_group;\n" ::: "memory");
}
template <int N>
__device__ __forceinline__ void cp_wait() {
    asm volatile("cp.async.wait_group %0;\n" :: "n"(N) : "memory");
}

// ---------------------------------------------------------------------------
// Fused kernel. One warp = one HALF-session (1024 trials); lane l = the
// 32-trial chunk [l*32, l*32+32) of that half (+16 warmup trials).
//   1. cp.async 12 KB of raw trials into smem (4 commit groups of 3 KB)
//   2. 32 ballot rounds pack bits; lane l keeps word l (conflict-free LDS:
//      bank = 3*lane mod 32 is a bijection)
//   3. shfl_up provides warmup bits; h==1 lane 0 gets them from a tiny
//      global read of the previous half's last 16 trials
//   4. R13-proven recurrence per lane; outputs staged into the SAME smem
//      buffer (input data dead after packing), flushed as 16 coalesced
//      STG.128 rounds (warp output = one contiguous 8 KB block)
// ---------------------------------------------------------------------------
__global__ void __launch_bounds__(128)
fused_kernel(const float* __restrict__ in,
             const float* __restrict__ p_stay_raw,
             const float* __restrict__ c_raw,
             float* __restrict__ out) {
    __shared__ __align__(16) char buf[4][12288];   // 49152 B (48 KB exactly)

    const int lane  = threadIdx.x & 31;
    const int wid   = threadIdx.x >> 5;
    const int gwarp = blockIdx.x * 4 + wid;
    const int s     = gwarp >> 1;
    const int h     = gwarp & 1;

    const char* src = (const char*)in + (long)s * (NTRIALS * 12) + h * (HALFT * 12);
    const uint32_t sb = (uint32_t)__cvta_generic_to_shared(&buf[wid][0]);

    // ---- 1. stage 12 KB in 4 commit groups of 6x512 B ----
#pragma unroll
    for (int g = 0; g < 4; g++) {
#pragma unroll
        for (int r = 0; r < 6; r++) {
            int off = (g * 6 + r) * 512 + lane * 16;
            cp_async16(sb + off, src + off);
        }
        cp_commit();
    }

    // model constants (overlap with cp.async latency)
    const float pv = 1.0f / (1.0f + __expf(-p_stay_raw[0]));
    const float cv = 1.0f / (1.0f + __expf(-c_raw[0]));
    const float A  = 0.5f * (1.0f + cv);
    const float B  = 0.5f * (1.0f - cv);
    const float q  = 0.5f * (1.0f + pv);
    const float qm = 0.5f * (1.0f - pv);

    // ---- 3a. h==1: pack the previous half's last 16 trials from global ----
    uint32_t pw = 0;
    if (h) {
        const float* gp = in + ((long)s * NTRIALS + HALFT - 16 + (lane & 15)) * 3;
        float cl = gp[0];
        float o  = gp[2];
        pw = __ballot_sync(0xFFFFFFFFu, (lane < 16) && (cl == o)) << 16;
    }

    // ---- 2. ballot-pack 32 words; lane l keeps word l ----
    const float* sf = (const float*)&buf[wid][0];
    uint32_t myw = 0;
#pragma unroll
    for (int g = 0; g < 4; g++) {
        switch (g) {
            case 0: cp_wait<3>(); break;
            case 1: cp_wait<2>(); break;
            case 2: cp_wait<1>(); break;
            default: cp_wait<0>(); break;
        }
        __syncwarp();
#pragma unroll
        for (int k = 0; k < 8; k++) {
            const int w = g * 8 + k;
            float cl = sf[w * 96 + lane * 3];
            float o  = sf[w * 96 + lane * 3 + 2];
            uint32_t bits = __ballot_sync(0xFFFFFFFFu, cl == o);
            if (lane == w) myw = bits;
        }
    }

    // ---- 3b. warmup word: high 16 bits of previous lane's word ----
    uint32_t wp = __shfl_up_sync(0xFFFFFFFFu, myw, 1);
    if (lane == 0) wp = pw;

    // ---- 4. filter (R13-proven math) ----
    float v0 = 0.5f, v1 = 0.5f;

    if (h + lane) {   // warmup for every chunk except global chunk 0
#pragma unroll
        for (int i = 0; i < FWARM; i++) {
            float e0 = ((wp >> (16 + i)) & 1u) ? A : B;
            float u0 = e0 * v0;
            float u1 = fmaf(-e0, v1, v1);
            float sm = u0 + u1;
            float a  = fmaf(q, u0, qm * u1);
            v0 = a;
            v1 = sm - a;
        }
        float r = frcp_fast(v0 + v1);
        v0 *= r; v1 *= r;
    }

    __syncwarp();   // pack reads complete before staging overwrites buf
    float4* stage4 = (float4*)&buf[wid][0];
    float4* ob4 = stage4 + lane * 17;   // 272 B stride: conflict-free STS.128

#pragma unroll
    for (int g = 0; g < 2; g++) {
        float rlast = 1.0f;
        float px = 0.0f;
#pragma unroll
        for (int i = 0; i < 16; i++) {
            float e0 = ((myw >> (g * 16 + i)) & 1u) ? A : B;
            float u0 = e0 * v0;
            float u1 = fmaf(-e0, v1, v1);
            float sm = u0 + u1;
            float a  = fmaf(q, u0, qm * u1);
            float r  = frcp_fast(sm);       // off-chain: outputs only
            float x  = a * r;
            if (i & 1) {
                ob4[g * 8 + (i >> 1)] = make_float4(px, 1.0f - px, x, 1.0f - x);
            } else {
                px = x;
            }
            if (i == 15) rlast = r;
            v0 = a;
            v1 = sm - a;
        }
        v0 *= rlast; v1 *= rlast;           // exact renorm, off the chain tail
    }

    // ---- 5. flush: warp output = contiguous 8 KB, 16 coalesced STG.128 ----
    __syncwarp();
    float4* og4 = (float4*)out + (long)s * (NTRIALS / 2) + h * (HALFT / 2);
#pragma unroll
    for (int j = 0; j < 16; j++) {
        int g = j * 32 + lane;              // 0..511 float4 of this half
        og4[g] = stage4[(g >> 4) * 17 + (g & 15)];
    }
}

extern "C" void kernel_launch(void* const* d_in, const int* in_sizes, int n_in,
                              void* d_out, int out_size) {
    const float* in   = (const float*)d_in[0];
    const float* praw = (const float*)d_in[1];
    const float* craw = (const float*)d_in[2];
    float* out = (float*)d_out;

    // 4096 sessions x 2 halves = 8192 warps = 2048 blocks of 128 threads
    fused_kernel<<<NSESS * 2 / 4, 128>>>(in, praw, craw, out);
}